// round 1
// baseline (speedup 1.0000x reference)
#include <cuda_runtime.h>

#define BSZ    8
#define TLEN   4096
#define DH     256
#define NHEAD  64
#define NPAIR  128               // 256 state dims / 2
#define LCHUNK 256
#define NCHUNK (TLEN / LCHUNK)   // 16

typedef unsigned long long ull;

// ---------------- device scratch (static; no allocations) ----------------
__device__ float  g_Wt  [DH * DH];            // W transposed: [d][n]
__device__ float  g_Ceff[DH * DH];            // [dout][n]
__device__ float2 g_lam [NPAIR];              // (gamma*cos th, gamma*sin th)
__device__ float2 g_lamL[NPAIR];              // lambda^LCHUNK
__device__ float  g_V   [BSZ * TLEN * DH];    // V then S, layout [(b*T+t)][n]
__device__ float2 g_carry[BSZ * NCHUNK * NPAIR];
__device__ int    g_flag [BSZ * NCHUNK];
__device__ int    g_ticket;

// ---------------- helpers ----------------
__device__ __forceinline__ ull fma2(ull a, ull b, ull c) {
    ull d;
    asm("fma.rn.f32x2 %0, %1, %2, %3;" : "=l"(d) : "l"(a), "l"(b), "l"(c));
    return d;
}
__device__ __forceinline__ float lo32(ull v) { return __uint_as_float((unsigned)v); }
__device__ __forceinline__ float hi32(ull v) { return __uint_as_float((unsigned)(v >> 32)); }

// ============================================================================
// Setup: per-head expm(skew), fold P into B_norm -> W, P^T into C -> C_eff,
// lambdas, and reset scan flags/ticket. grid = 64 (one block per head).
// ============================================================================
__global__ void setup_kernel(const float* __restrict__ thetas_log,
                             const float* __restrict__ P_param,
                             const float* __restrict__ B_param,
                             const float* __restrict__ C,
                             const float* __restrict__ gamma_log)
{
    int h = blockIdx.x;
    int tid = threadIdx.x;

    __shared__ double sA[16], sEd[16], sTm[16], sTmp[16];
    __shared__ float  sRed[256];
    __shared__ float  sEf[16];
    __shared__ float  sNrm;

    if (h == 0) {
        if (tid < BSZ * NCHUNK) g_flag[tid] = 0;
        if (tid == 128) g_ticket = 0;
    }

    // trace(B B^T) for this head
    float part = 0.f;
    for (int i = tid; i < 1024; i += 256) {
        float v = B_param[h * 1024 + i];
        part += v * v;
    }
    sRed[tid] = part;
    __syncthreads();
    for (int s = 128; s > 0; s >>= 1) {
        if (tid < s) sRed[tid] += sRed[tid + s];
        __syncthreads();
    }

    // skew and expm via Taylor (double; ||A|| << 1, 24 terms converge fully)
    if (tid < 16) {
        int i = tid >> 2, j = tid & 3;
        sA[tid]  = (double)P_param[h * 16 + tid] - (double)P_param[h * 16 + j * 4 + i];
        sEd[tid] = (i == j) ? 1.0 : 0.0;
        sTm[tid] = sEd[tid];
    }
    __syncthreads();
    for (int k = 1; k <= 24; ++k) {
        if (tid < 16) {
            int i = tid >> 2, j = tid & 3;
            double acc = 0.0;
#pragma unroll
            for (int m = 0; m < 4; m++) acc += sTm[i * 4 + m] * sA[m * 4 + j];
            sTmp[tid] = acc / (double)k;
        }
        __syncthreads();
        if (tid < 16) { sTm[tid] = sTmp[tid]; sEd[tid] += sTmp[tid]; }
        __syncthreads();
    }

    if (tid == 0) {
        double gl    = (double)gamma_log[h];
        double eg    = exp(gl);
        double gamma = exp(-eg);
        sNrm = (float)sqrt((1.0 - gamma * gamma) / (double)sRed[0]);
        double gL = exp(-(double)LCHUNK * eg);
        for (int j = 0; j < 2; j++) {
            double th = exp((double)thetas_log[h * 2 + j]);
            g_lam[h * 2 + j] = make_float2((float)(gamma * cos(th)),
                                           (float)(gamma * sin(th)));
            double a = fmod((double)LCHUNK * th, 6.283185307179586476925286766559);
            g_lamL[h * 2 + j] = make_float2((float)(gL * cos(a)),
                                            (float)(gL * sin(a)));
        }
    }
    if (tid < 16) sEf[tid] = (float)sEd[tid];
    __syncthreads();

    float nrm = sNrm;
    // W rows: W[h*4+N][d] = nrm * sum_n P[N][n] * B_param[n][d]  (stored transposed)
    for (int o = tid; o < 1024; o += 256) {
        int N = o >> 8, d = o & 255;
        float w = 0.f;
#pragma unroll
        for (int n = 0; n < 4; n++) w += sEf[N * 4 + n] * B_param[h * 1024 + n * 256 + d];
        g_Wt[d * 256 + h * 4 + N] = nrm * w;
    }
    // C_eff[Do][h*4+N] = sum_n C[Do][h*4+n] * P[N][n]
    for (int o = tid; o < 1024; o += 256) {
        int N = o >> 8, Do = o & 255;
        float c = 0.f;
#pragma unroll
        for (int n = 0; n < 4; n++) c += C[Do * 256 + h * 4 + n] * sEf[N * 4 + n];
        g_Ceff[Do * 256 + h * 4 + N] = c;
    }
}

// ============================================================================
// GEMM 1: V[(b*T+t)][n] = sum_d u[b][d][t] * Wt[d][n]
// Tiles 128(t) x 64(n), K=16 steps, fp32x2 packed along t.
// ============================================================================
__global__ __launch_bounds__(256) void proj_kernel(const float* __restrict__ U)
{
    __shared__ __align__(16) float  As[16][132];   // [k][t], padded
    __shared__ __align__(16) float2 Bs[16][66];    // [k][n] pre-splatted

    int b  = blockIdx.z;
    int t0 = blockIdx.x * 128;
    int n0 = blockIdx.y * 64;
    const float* Ub = U + b * (DH * TLEN);
    int tid = threadIdx.x;
    int tx = tid & 15, ty = tid >> 4;

    ull acc[4][4];
#pragma unroll
    for (int i = 0; i < 4; i++)
#pragma unroll
        for (int j = 0; j < 4; j++) acc[i][j] = 0ull;

    for (int d0 = 0; d0 < 256; d0 += 16) {
#pragma unroll
        for (int r = 0; r < 2; r++) {
            int q = tid + r * 256;
            int kk = q >> 5, tq = (q & 31) << 2;
            *(float4*)&As[kk][tq] = *(const float4*)&Ub[(d0 + kk) * TLEN + t0 + tq];
        }
        {
            int kk = tid >> 4, nq = (tid & 15) << 2;
            float4 w = *(const float4*)&g_Wt[(d0 + kk) * 256 + n0 + nq];
            Bs[kk][nq + 0] = make_float2(w.x, w.x);
            Bs[kk][nq + 1] = make_float2(w.y, w.y);
            Bs[kk][nq + 2] = make_float2(w.z, w.z);
            Bs[kk][nq + 3] = make_float2(w.w, w.w);
        }
        __syncthreads();
#pragma unroll
        for (int kk = 0; kk < 16; kk++) {
            const ulonglong2* ap = (const ulonglong2*)&As[kk][ty * 8];
            ulonglong2 a01 = ap[0], a23 = ap[1];
            ull a[4] = { a01.x, a01.y, a23.x, a23.y };
            const ulonglong2* bp = (const ulonglong2*)&Bs[kk][tx * 4];
            ulonglong2 b01 = bp[0], b23 = bp[1];
            ull bb[4] = { b01.x, b01.y, b23.x, b23.y };
#pragma unroll
            for (int i = 0; i < 4; i++)
#pragma unroll
                for (int j = 0; j < 4; j++)
                    acc[i][j] = fma2(a[i], bb[j], acc[i][j]);
        }
        __syncthreads();
    }

    int nbase = n0 + tx * 4;
#pragma unroll
    for (int i = 0; i < 4; i++) {
        int te = t0 + ty * 8 + 2 * i;
        float4 lo = make_float4(lo32(acc[i][0]), lo32(acc[i][1]),
                                lo32(acc[i][2]), lo32(acc[i][3]));
        float4 hi = make_float4(hi32(acc[i][0]), hi32(acc[i][1]),
                                hi32(acc[i][2]), hi32(acc[i][3]));
        *(float4*)&g_V[(b * TLEN + te) * 256 + nbase]     = lo;
        *(float4*)&g_V[(b * TLEN + te + 1) * 256 + nbase] = hi;
    }
}

// ============================================================================
// Scan: s_t = gamma*R(theta)*s_{t-1} + v_t, per (batch, complex pair).
// Single-pass chunked scan with decoupled lookback, ticket-ordered for
// forward progress. 128 blocks x 128 threads. In-place on g_V.
// ============================================================================
__global__ __launch_bounds__(NPAIR) void scan_kernel()
{
    __shared__ int s_tk;
    if (threadIdx.x == 0) s_tk = atomicAdd(&g_ticket, 1);
    __syncthreads();
    int tk    = s_tk;
    int chunk = tk >> 3;      // chunk major -> predecessors always scheduled first
    int b     = tk & 7;
    int p     = threadIdx.x;

    float2 lam = g_lam[p];
    float lc = lam.x, ls = lam.y;
    int base = (b * TLEN + chunk * LCHUNK) * 256 + 2 * p;

    // phase 1: local scan from zero state
    float s0 = 0.f, s1 = 0.f;
#pragma unroll 4
    for (int t = 0; t < LCHUNK; t++) {
        float2 v = *(const float2*)&g_V[base + t * 256];
        float n0 = fmaf(lc, s0, fmaf(-ls, s1, v.x));
        float n1 = fmaf(ls, s0, fmaf( lc, s1, v.y));
        s0 = n0; s1 = n1;
    }

    // lookback
    float e0 = 0.f, e1 = 0.f;
    int idx = b * NCHUNK + chunk;
    if (chunk > 0) {
        int prev = idx - 1;
        if (p == 0) {
            while (atomicAdd(&g_flag[prev], 0) == 0) __nanosleep(40);
        }
        __syncthreads();
        float2 e = __ldcg(&g_carry[prev * NPAIR + p]);
        e0 = e.x; e1 = e.y;
    }
    float2 mL = g_lamL[p];
    float i0 = fmaf(mL.x, e0, fmaf(-mL.y, e1, s0));
    float i1 = fmaf(mL.y, e0, fmaf( mL.x, e1, s1));
    __stcg(&g_carry[idx * NPAIR + p], make_float2(i0, i1));
    __threadfence();
    __syncthreads();
    if (p == 0) atomicExch(&g_flag[idx], 1);

    // phase 2: rescan with carry, write final states
    s0 = e0; s1 = e1;
#pragma unroll 4
    for (int t = 0; t < LCHUNK; t++) {
        float2 v = *(const float2*)&g_V[base + t * 256];
        float n0 = fmaf(lc, s0, fmaf(-ls, s1, v.x));
        float n1 = fmaf(ls, s0, fmaf( lc, s1, v.y));
        s0 = n0; s1 = n1;
        *(float2*)&g_V[base + t * 256] = make_float2(s0, s1);
    }
}

// ============================================================================
// GEMM 2: Y[b][dout][t] = sum_n C_eff[dout][n]*S[(b*T+t)][n] + D[dout]*u[b][dout][t]
// Tiles 64(dout) x 128(t), K=16 steps, fp32x2 packed along t.
// ============================================================================
__global__ __launch_bounds__(256) void out_kernel(const float* __restrict__ U,
                                                  const float* __restrict__ Dvec,
                                                  float* __restrict__ Y)
{
    __shared__ __align__(16) float2 Asp[16][66];   // [k][dout] pre-splatted C_eff
    __shared__ __align__(16) float  Bs[16][132];   // [k][t] transposed S

    int b  = blockIdx.z;
    int t0 = blockIdx.x * 128;
    int m0 = blockIdx.y * 64;
    int tid = threadIdx.x;
    int tx = tid & 15, ty = tid >> 4;

    ull acc[4][4];   // [dout j][t-pair i]
#pragma unroll
    for (int j = 0; j < 4; j++)
#pragma unroll
        for (int i = 0; i < 4; i++) acc[j][i] = 0ull;

    for (int k0 = 0; k0 < 256; k0 += 16) {
        {
            int mm = tid >> 2, kq = (tid & 3) << 2;
            float4 c4 = *(const float4*)&g_Ceff[(m0 + mm) * 256 + k0 + kq];
            Asp[kq + 0][mm] = make_float2(c4.x, c4.x);
            Asp[kq + 1][mm] = make_float2(c4.y, c4.y);
            Asp[kq + 2][mm] = make_float2(c4.z, c4.z);
            Asp[kq + 3][mm] = make_float2(c4.w, c4.w);
        }
#pragma unroll
        for (int r = 0; r < 2; r++) {
            int q = tid + r * 256;
            int tt = q >> 2, kq = (q & 3) << 2;
            float4 s4 = *(const float4*)&g_V[(b * TLEN + t0 + tt) * 256 + k0 + kq];
            Bs[kq + 0][tt] = s4.x;
            Bs[kq + 1][tt] = s4.y;
            Bs[kq + 2][tt] = s4.z;
            Bs[kq + 3][tt] = s4.w;
        }
        __syncthreads();
#pragma unroll
        for (int kk = 0; kk < 16; kk++) {
            ull a[4];
#pragma unroll
            for (int j = 0; j < 4; j++)
                a[j] = *(const ull*)&Asp[kk][ty * 4 + j];
            const ulonglong2* bp = (const ulonglong2*)&Bs[kk][tx * 8];
            ulonglong2 b01 = bp[0], b23 = bp[1];
            ull bb[4] = { b01.x, b01.y, b23.x, b23.y };
#pragma unroll
            for (int j = 0; j < 4; j++)
#pragma unroll
                for (int i = 0; i < 4; i++)
                    acc[j][i] = fma2(a[j], bb[i], acc[j][i]);
        }
        __syncthreads();
    }

#pragma unroll
    for (int j = 0; j < 4; j++) {
        int dout = m0 + ty * 4 + j;
        float dv = Dvec[dout];
        const float* urow = U + b * (DH * TLEN) + dout * TLEN + t0 + tx * 8;
        float*       yrow = Y + b * (DH * TLEN) + dout * TLEN + t0 + tx * 8;
        float4 u0 = *(const float4*)&urow[0];
        float4 u1 = *(const float4*)&urow[4];
        float4 r0 = make_float4(lo32(acc[j][0]) + dv * u0.x,
                                hi32(acc[j][0]) + dv * u0.y,
                                lo32(acc[j][1]) + dv * u0.z,
                                hi32(acc[j][1]) + dv * u0.w);
        float4 r1 = make_float4(lo32(acc[j][2]) + dv * u1.x,
                                hi32(acc[j][2]) + dv * u1.y,
                                lo32(acc[j][3]) + dv * u1.z,
                                hi32(acc[j][3]) + dv * u1.w);
        *(float4*)&yrow[0] = r0;
        *(float4*)&yrow[4] = r1;
    }
}

// ============================================================================
extern "C" void kernel_launch(void* const* d_in, const int* in_sizes, int n_in,
                              void* d_out, int out_size)
{
    const float* u          = (const float*)d_in[0];
    const float* thetas_log = (const float*)d_in[1];
    const float* P_param    = (const float*)d_in[2];
    const float* B_param    = (const float*)d_in[3];
    const float* C          = (const float*)d_in[4];
    const float* Dv         = (const float*)d_in[5];
    const float* gamma_log  = (const float*)d_in[6];
    float* Y = (float*)d_out;

    setup_kernel<<<64, 256>>>(thetas_log, P_param, B_param, C, gamma_log);
    proj_kernel<<<dim3(TLEN / 128, DH / 64, BSZ), 256>>>(u);
    scan_kernel<<<BSZ * NCHUNK, NPAIR>>>();
    out_kernel<<<dim3(TLEN / 128, DH / 64, BSZ), 256>>>(u, Dv, Y);
}

// round 2
// speedup vs baseline: 1.2606x; 1.2606x over previous
#include <cuda_runtime.h>

#define BSZ    8
#define TLEN   4096
#define DH     256
#define NHEAD  64
#define NPAIR  128               // 256 state dims / 2
#define LCHUNK 256
#define NCHUNK (TLEN / LCHUNK)   // 16

typedef unsigned long long ull;

// ---------------- device scratch (static; no allocations) ----------------
__device__ float  g_Wt  [DH * DH];            // W transposed: [d][n]
__device__ float  g_Ceff[DH * DH];            // [dout][n]
__device__ float2 g_lam [NPAIR];              // (gamma*cos th, gamma*sin th)
__device__ float2 g_lamL[NPAIR];              // lambda^LCHUNK
__device__ float  g_V   [BSZ * TLEN * DH];    // V then S, layout [(b*T+t)][n]
__device__ float2 g_carry[BSZ * NCHUNK * NPAIR];
__device__ int    g_flag [BSZ * NCHUNK];

// ---------------- helpers ----------------
__device__ __forceinline__ ull fma2(ull a, ull b, ull c) {
    ull d;
    asm("fma.rn.f32x2 %0, %1, %2, %3;" : "=l"(d) : "l"(a), "l"(b), "l"(c));
    return d;
}
__device__ __forceinline__ float lo32(ull v) { return __uint_as_float((unsigned)v); }
__device__ __forceinline__ float hi32(ull v) { return __uint_as_float((unsigned)(v >> 32)); }

// ============================================================================
// Setup: per-head expm(skew), fold P into B_norm -> W, P^T into C -> C_eff,
// lambdas, and reset scan flags. grid = 64 (one block per head).
// ============================================================================
__global__ void setup_kernel(const float* __restrict__ thetas_log,
                             const float* __restrict__ P_param,
                             const float* __restrict__ B_param,
                             const float* __restrict__ C,
                             const float* __restrict__ gamma_log)
{
    int h = blockIdx.x;
    int tid = threadIdx.x;

    __shared__ double sA[16], sEd[16], sTm[16], sTmp[16];
    __shared__ float  sRed[256];
    __shared__ float  sEf[16];
    __shared__ float  sNrm;

    if (h == 0 && tid < BSZ * NCHUNK) g_flag[tid] = 0;

    // trace(B B^T) for this head
    float part = 0.f;
    for (int i = tid; i < 1024; i += 256) {
        float v = B_param[h * 1024 + i];
        part += v * v;
    }
    sRed[tid] = part;
    __syncthreads();
    for (int s = 128; s > 0; s >>= 1) {
        if (tid < s) sRed[tid] += sRed[tid + s];
        __syncthreads();
    }

    // skew and expm via Taylor (double; ||A|| << 1, 24 terms converge fully)
    if (tid < 16) {
        int i = tid >> 2, j = tid & 3;
        sA[tid]  = (double)P_param[h * 16 + tid] - (double)P_param[h * 16 + j * 4 + i];
        sEd[tid] = (i == j) ? 1.0 : 0.0;
        sTm[tid] = sEd[tid];
    }
    __syncthreads();
    for (int k = 1; k <= 24; ++k) {
        if (tid < 16) {
            int i = tid >> 2, j = tid & 3;
            double acc = 0.0;
#pragma unroll
            for (int m = 0; m < 4; m++) acc += sTm[i * 4 + m] * sA[m * 4 + j];
            sTmp[tid] = acc / (double)k;
        }
        __syncthreads();
        if (tid < 16) { sTm[tid] = sTmp[tid]; sEd[tid] += sTmp[tid]; }
        __syncthreads();
    }

    if (tid == 0) {
        double gl    = (double)gamma_log[h];
        double eg    = exp(gl);
        double gamma = exp(-eg);
        sNrm = (float)sqrt((1.0 - gamma * gamma) / (double)sRed[0]);
        double gL = exp(-(double)LCHUNK * eg);
        for (int j = 0; j < 2; j++) {
            double th = exp((double)thetas_log[h * 2 + j]);
            g_lam[h * 2 + j] = make_float2((float)(gamma * cos(th)),
                                           (float)(gamma * sin(th)));
            double a = fmod((double)LCHUNK * th, 6.283185307179586476925286766559);
            g_lamL[h * 2 + j] = make_float2((float)(gL * cos(a)),
                                            (float)(gL * sin(a)));
        }
    }
    if (tid < 16) sEf[tid] = (float)sEd[tid];
    __syncthreads();

    float nrm = sNrm;
    // W rows: W[h*4+N][d] = nrm * sum_n P[N][n] * B_param[n][d]  (stored transposed)
    for (int o = tid; o < 1024; o += 256) {
        int N = o >> 8, d = o & 255;
        float w = 0.f;
#pragma unroll
        for (int n = 0; n < 4; n++) w += sEf[N * 4 + n] * B_param[h * 1024 + n * 256 + d];
        g_Wt[d * 256 + h * 4 + N] = nrm * w;
    }
    // C_eff[Do][h*4+N] = sum_n C[Do][h*4+n] * P[N][n]
    for (int o = tid; o < 1024; o += 256) {
        int N = o >> 8, Do = o & 255;
        float c = 0.f;
#pragma unroll
        for (int n = 0; n < 4; n++) c += C[Do * 256 + h * 4 + n] * sEf[N * 4 + n];
        g_Ceff[Do * 256 + h * 4 + N] = c;
    }
}

// ============================================================================
// GEMM 1: V[(b*T+t)][n] = sum_d u[b][d][t] * Wt[d][n]
// Block tile 256(t) x 64(n); thread tile 8 t-pairs x 4 n; fp32x2 along t.
// Per kk: 6 LDS.128 feed 32 FFMA2.
// ============================================================================
__global__ __launch_bounds__(256, 2) void proj_kernel(const float* __restrict__ U)
{
    __shared__ __align__(16) float  As[16][256];   // [k][t]
    __shared__ __align__(16) float2 Ws[16][66];    // [k][n] pre-splatted, padded

    int b  = blockIdx.z;
    int t0 = blockIdx.x * 256;
    int n0 = blockIdx.y * 64;
    const float* Ub = U + b * (DH * TLEN);
    int tid = threadIdx.x;
    int tx = tid & 15;         // t-group: pairs {32j + 2tx + r}
    int ty = tid >> 4;         // n-group: n = n0 + 4*ty .. +3

    ull acc[4][8];             // [n][slot], slot = 2j+r
#pragma unroll
    for (int m = 0; m < 4; m++)
#pragma unroll
        for (int s = 0; s < 8; s++) acc[m][s] = 0ull;

    for (int d0 = 0; d0 < 256; d0 += 16) {
#pragma unroll
        for (int r = 0; r < 4; r++) {
            int idx = tid + r * 256;             // 0..1023 float4 slots
            int kk = idx >> 6;                   // 64 float4 per row
            int tq = (idx & 63) << 2;
            *(float4*)&As[kk][tq] = *(const float4*)&Ub[(d0 + kk) * TLEN + t0 + tq];
        }
        {
            int kk = tid >> 4;                   // 16 float4 per row
            int nq = (tid & 15) << 2;
            float4 w = *(const float4*)&g_Wt[(d0 + kk) * 256 + n0 + nq];
            Ws[kk][nq + 0] = make_float2(w.x, w.x);
            Ws[kk][nq + 1] = make_float2(w.y, w.y);
            Ws[kk][nq + 2] = make_float2(w.z, w.z);
            Ws[kk][nq + 3] = make_float2(w.w, w.w);
        }
        __syncthreads();
#pragma unroll
        for (int kk = 0; kk < 16; kk++) {
            const ulonglong2* wp = (const ulonglong2*)&Ws[kk][ty * 4];
            ulonglong2 w01 = wp[0], w23 = wp[1];
            ull a[4] = { w01.x, w01.y, w23.x, w23.y };
            ull bf[8];
#pragma unroll
            for (int j = 0; j < 4; j++) {
                ulonglong2 v = *(const ulonglong2*)&As[kk][(32 * j + 2 * tx) * 2];
                bf[2 * j] = v.x; bf[2 * j + 1] = v.y;
            }
#pragma unroll
            for (int m = 0; m < 4; m++)
#pragma unroll
                for (int s = 0; s < 8; s++)
                    acc[m][s] = fma2(a[m], bf[s], acc[m][s]);
        }
        __syncthreads();
    }

    // epilogue: write V[t][n0+4ty .. +3]
    int nb = n0 + ty * 4;
#pragma unroll
    for (int j = 0; j < 4; j++) {
        int tb = t0 + 64 * j + 4 * tx;
        float4 r0 = make_float4(lo32(acc[0][2*j]),   lo32(acc[1][2*j]),
                                lo32(acc[2][2*j]),   lo32(acc[3][2*j]));
        float4 r1 = make_float4(hi32(acc[0][2*j]),   hi32(acc[1][2*j]),
                                hi32(acc[2][2*j]),   hi32(acc[3][2*j]));
        float4 r2 = make_float4(lo32(acc[0][2*j+1]), lo32(acc[1][2*j+1]),
                                lo32(acc[2][2*j+1]), lo32(acc[3][2*j+1]));
        float4 r3 = make_float4(hi32(acc[0][2*j+1]), hi32(acc[1][2*j+1]),
                                hi32(acc[2][2*j+1]), hi32(acc[3][2*j+1]));
        *(float4*)&g_V[(b * TLEN + tb + 0) * 256 + nb] = r0;
        *(float4*)&g_V[(b * TLEN + tb + 1) * 256 + nb] = r1;
        *(float4*)&g_V[(b * TLEN + tb + 2) * 256 + nb] = r2;
        *(float4*)&g_V[(b * TLEN + tb + 3) * 256 + nb] = r3;
    }
}

// ============================================================================
// Scan: s_t = gamma*R(theta)*s_{t-1} + v_t. 128 blocks (all resident) x 128
// threads; decoupled lookback, in-place on g_V (L2-resident).
// ============================================================================
__global__ __launch_bounds__(NPAIR) void scan_kernel()
{
    int b     = blockIdx.x & 7;
    int chunk = blockIdx.x >> 3;
    int p     = threadIdx.x;

    float2 lam = g_lam[p];
    float lc = lam.x, ls = lam.y;
    int base = (b * TLEN + chunk * LCHUNK) * 256 + 2 * p;

    // phase 1: local scan from zero state
    float s0 = 0.f, s1 = 0.f;
#pragma unroll 4
    for (int t = 0; t < LCHUNK; t++) {
        float2 v = *(const float2*)&g_V[base + t * 256];
        float n0 = fmaf(lc, s0, fmaf(-ls, s1, v.x));
        float n1 = fmaf(ls, s0, fmaf( lc, s1, v.y));
        s0 = n0; s1 = n1;
    }

    // lookback
    float e0 = 0.f, e1 = 0.f;
    int idx = b * NCHUNK + chunk;
    if (chunk > 0) {
        int prev = idx - 1;
        if (p == 0) {
            while (atomicAdd(&g_flag[prev], 0) == 0) __nanosleep(40);
        }
        __syncthreads();
        float2 e = __ldcg(&g_carry[prev * NPAIR + p]);
        e0 = e.x; e1 = e.y;
    }
    float2 mL = g_lamL[p];
    float i0 = fmaf(mL.x, e0, fmaf(-mL.y, e1, s0));
    float i1 = fmaf(mL.y, e0, fmaf( mL.x, e1, s1));
    __stcg(&g_carry[idx * NPAIR + p], make_float2(i0, i1));
    __threadfence();
    __syncthreads();
    if (p == 0) atomicExch(&g_flag[idx], 1);

    // phase 2: rescan with carry, write final states
    s0 = e0; s1 = e1;
#pragma unroll 4
    for (int t = 0; t < LCHUNK; t++) {
        float2 v = *(const float2*)&g_V[base + t * 256];
        float n0 = fmaf(lc, s0, fmaf(-ls, s1, v.x));
        float n1 = fmaf(ls, s0, fmaf( lc, s1, v.y));
        s0 = n0; s1 = n1;
        *(float2*)&g_V[base + t * 256] = make_float2(s0, s1);
    }
}

// ============================================================================
// GEMM 2: Y[b][dout][t] = sum_n C_eff[dout][n]*S[t][n] + D[dout]*u[b][dout][t]
// Block tile 64(dout) x 256(t); thread tile 4 dout x 8 t-pairs.
// ============================================================================
__global__ __launch_bounds__(256, 2) void out_kernel(const float* __restrict__ U,
                                                     const float* __restrict__ Dvec,
                                                     float* __restrict__ Y)
{
    __shared__ __align__(16) float2 Cs[16][66];    // [k][dout] pre-splatted
    __shared__ __align__(16) float  Ss[16][264];   // [k][t] transposed S (pad 264)

    int b  = blockIdx.z;
    int t0 = blockIdx.x * 256;
    int m0 = blockIdx.y * 64;
    int tid = threadIdx.x;
    int tx = tid & 15;
    int ty = tid >> 4;        // dout group: m0 + 4*ty .. +3

    ull acc[4][8];
#pragma unroll
    for (int m = 0; m < 4; m++)
#pragma unroll
        for (int s = 0; s < 8; s++) acc[m][s] = 0ull;

    for (int k0 = 0; k0 < 256; k0 += 16) {
        {
            int mm = tid >> 2, kq = (tid & 3) << 2;    // 64 dout x 4 float4-chunks
            float4 c4 = *(const float4*)&g_Ceff[(m0 + mm) * 256 + k0 + kq];
            Cs[kq + 0][mm] = make_float2(c4.x, c4.x);
            Cs[kq + 1][mm] = make_float2(c4.y, c4.y);
            Cs[kq + 2][mm] = make_float2(c4.z, c4.z);
            Cs[kq + 3][mm] = make_float2(c4.w, c4.w);
        }
#pragma unroll
        for (int r = 0; r < 4; r++) {
            int idx = tid + r * 256;                   // 1024 float4 = 256t x 16k
            int tt = idx >> 2, kq = (idx & 3) << 2;
            float4 s4 = *(const float4*)&g_V[(b * TLEN + t0 + tt) * 256 + k0 + kq];
            Ss[kq + 0][tt] = s4.x;
            Ss[kq + 1][tt] = s4.y;
            Ss[kq + 2][tt] = s4.z;
            Ss[kq + 3][tt] = s4.w;
        }
        __syncthreads();
#pragma unroll
        for (int kk = 0; kk < 16; kk++) {
            const ulonglong2* cp = (const ulonglong2*)&Cs[kk][ty * 4];
            ulonglong2 c01 = cp[0], c23 = cp[1];
            ull a[4] = { c01.x, c01.y, c23.x, c23.y };
            ull bf[8];
#pragma unroll
            for (int j = 0; j < 4; j++) {
                ulonglong2 v = *(const ulonglong2*)&Ss[kk][(32 * j + 2 * tx) * 2];
                bf[2 * j] = v.x; bf[2 * j + 1] = v.y;
            }
#pragma unroll
            for (int m = 0; m < 4; m++)
#pragma unroll
                for (int s = 0; s < 8; s++)
                    acc[m][s] = fma2(a[m], bf[s], acc[m][s]);
        }
        __syncthreads();
    }

    // epilogue: + D * u, write Y [b][dout][t]
    float4 dv = *(const float4*)&Dvec[m0 + ty * 4];
    float dva[4] = { dv.x, dv.y, dv.z, dv.w };
#pragma unroll
    for (int m = 0; m < 4; m++) {
        int dout = m0 + ty * 4 + m;
        const float* urow = U + b * (DH * TLEN) + dout * TLEN;
        float*       yrow = Y + b * (DH * TLEN) + dout * TLEN;
#pragma unroll
        for (int j = 0; j < 4; j++) {
            int tb = t0 + 64 * j + 4 * tx;
            float4 u4 = *(const float4*)&urow[tb];
            float4 r  = make_float4(lo32(acc[m][2*j])   + dva[m] * u4.x,
                                    hi32(acc[m][2*j])   + dva[m] * u4.y,
                                    lo32(acc[m][2*j+1]) + dva[m] * u4.z,
                                    hi32(acc[m][2*j+1]) + dva[m] * u4.w);
            *(float4*)&yrow[tb] = r;
        }
    }
}

// ============================================================================
extern "C" void kernel_launch(void* const* d_in, const int* in_sizes, int n_in,
                              void* d_out, int out_size)
{
    const float* u          = (const float*)d_in[0];
    const float* thetas_log = (const float*)d_in[1];
    const float* P_param    = (const float*)d_in[2];
    const float* B_param    = (const float*)d_in[3];
    const float* C          = (const float*)d_in[4];
    const float* Dv         = (const float*)d_in[5];
    const float* gamma_log  = (const float*)d_in[6];
    float* Y = (float*)d_out;

    setup_kernel<<<64, 256>>>(thetas_log, P_param, B_param, C, gamma_log);
    proj_kernel<<<dim3(TLEN / 256, DH / 64, BSZ), 256>>>(u);
    scan_kernel<<<BSZ * NCHUNK, NPAIR>>>();
    out_kernel<<<dim3(TLEN / 256, DH / 64, BSZ), 256>>>(u, Dv, Y);
}

// round 4
// speedup vs baseline: 2.0897x; 1.6577x over previous
#include <cuda_runtime.h>
#include <cuda_bf16.h>
#include <cstdint>

#define BSZ    8
#define TLEN   4096
#define DH     256
#define NPAIR  128
#define LCHUNK 256
#define NCHUNK (TLEN / LCHUNK)   // 16

// ---------------- device scratch (static; no allocations) ----------------
__device__ __align__(16) __nv_bfloat16 g_Whi[DH * DH];   // W [n][d]
__device__ __align__(16) __nv_bfloat16 g_Wlo[DH * DH];
__device__ __align__(16) __nv_bfloat16 g_Chi[DH * DH];   // C_eff [dout][n]
__device__ __align__(16) __nv_bfloat16 g_Clo[DH * DH];
__device__ __align__(16) __nv_bfloat16 g_UThi[BSZ * TLEN * DH];  // u^T [b][t][d]
__device__ __align__(16) __nv_bfloat16 g_UTlo[BSZ * TLEN * DH];
__device__ __align__(16) float         g_V   [BSZ * DH * TLEN];  // [b][n][t]
__device__ __align__(16) __nv_bfloat16 g_Shi[BSZ * TLEN * DH];   // [b][t][n]
__device__ __align__(16) __nv_bfloat16 g_Slo[BSZ * TLEN * DH];
__device__ float2 g_lam [NPAIR];
__device__ float2 g_lamL[NPAIR];
__device__ float2 g_carry[BSZ * NCHUNK * NPAIR];
__device__ int    g_flag [BSZ * NCHUNK];

// ---------------- PTX helpers (all sm_80+ portable) ----------------
__device__ __forceinline__ uint32_t smem_u32(const void* p) {
    uint32_t a;
    asm("{ .reg .u64 t; cvta.to.shared.u64 t, %1; cvt.u32.u64 %0, t; }" : "=r"(a) : "l"(p));
    return a;
}
__device__ __forceinline__ void cpa16(uint32_t dst, const void* src) {
    asm volatile("cp.async.cg.shared.global [%0], [%1], 16;" :: "r"(dst), "l"(src));
}
__device__ __forceinline__ void cpa_commit() { asm volatile("cp.async.commit_group;"); }

__device__ __forceinline__ void ldmx4(uint32_t* r, uint32_t addr) {
    asm volatile("ldmatrix.sync.aligned.m8n8.x4.shared.b16 {%0,%1,%2,%3}, [%4];"
                 : "=r"(r[0]), "=r"(r[1]), "=r"(r[2]), "=r"(r[3]) : "r"(addr));
}
__device__ __forceinline__ void mma_bf16(float* c, const uint32_t* a, uint32_t b0, uint32_t b1) {
    asm volatile("mma.sync.aligned.m16n8k16.row.col.f32.bf16.bf16.f32 "
                 "{%0,%1,%2,%3}, {%4,%5,%6,%7}, {%8,%9}, {%0,%1,%2,%3};"
                 : "+f"(c[0]), "+f"(c[1]), "+f"(c[2]), "+f"(c[3])
                 : "r"(a[0]), "r"(a[1]), "r"(a[2]), "r"(a[3]), "r"(b0), "r"(b1));
}
// xor swizzle for 64B rows (4 x 16B chunks): conflict-free ldmatrix + cp.async
__device__ __forceinline__ uint32_t swz64(int r, int ch) {
    return (uint32_t)(r * 64 + ((ch ^ ((r >> 1) & 3)) << 4));
}

// ============================================================================
// Setup: expm(skew) per head, fold into W=[n][d] and C_eff=[dout][n] (bf16 hi/lo)
// ============================================================================
__global__ void setup_kernel(const float* __restrict__ thetas_log,
                             const float* __restrict__ P_param,
                             const float* __restrict__ B_param,
                             const float* __restrict__ C,
                             const float* __restrict__ gamma_log)
{
    int h = blockIdx.x, tid = threadIdx.x;
    __shared__ double sA[16], sEd[16], sTm[16], sTmp[16];
    __shared__ float  sRed[256], sEf[16], sNrm;

    if (h == 0 && tid < BSZ * NCHUNK) g_flag[tid] = 0;

    float part = 0.f;
    for (int i = tid; i < 1024; i += 256) {
        float v = B_param[h * 1024 + i];
        part += v * v;
    }
    sRed[tid] = part;
    __syncthreads();
    for (int s = 128; s > 0; s >>= 1) {
        if (tid < s) sRed[tid] += sRed[tid + s];
        __syncthreads();
    }
    if (tid < 16) {
        int i = tid >> 2, j = tid & 3;
        sA[tid]  = (double)P_param[h * 16 + tid] - (double)P_param[h * 16 + j * 4 + i];
        sEd[tid] = (i == j) ? 1.0 : 0.0;
        sTm[tid] = sEd[tid];
    }
    __syncthreads();
    for (int k = 1; k <= 24; ++k) {
        if (tid < 16) {
            int i = tid >> 2, j = tid & 3;
            double acc = 0.0;
#pragma unroll
            for (int m = 0; m < 4; m++) acc += sTm[i * 4 + m] * sA[m * 4 + j];
            sTmp[tid] = acc / (double)k;
        }
        __syncthreads();
        if (tid < 16) { sTm[tid] = sTmp[tid]; sEd[tid] += sTmp[tid]; }
        __syncthreads();
    }
    if (tid == 0) {
        double gl = (double)gamma_log[h], eg = exp(gl), gamma = exp(-eg);
        sNrm = (float)sqrt((1.0 - gamma * gamma) / (double)sRed[0]);
        double gL = exp(-(double)LCHUNK * eg);
        for (int j = 0; j < 2; j++) {
            double th = exp((double)thetas_log[h * 2 + j]);
            g_lam[h * 2 + j] = make_float2((float)(gamma * cos(th)), (float)(gamma * sin(th)));
            double a = fmod((double)LCHUNK * th, 6.283185307179586476925286766559);
            g_lamL[h * 2 + j] = make_float2((float)(gL * cos(a)), (float)(gL * sin(a)));
        }
    }
    if (tid < 16) sEf[tid] = (float)sEd[tid];
    __syncthreads();
    float nrm = sNrm;
    for (int o = tid; o < 1024; o += 256) {
        int N = o >> 8, d = o & 255;
        float w = 0.f;
#pragma unroll
        for (int n = 0; n < 4; n++) w += sEf[N * 4 + n] * B_param[h * 1024 + n * 256 + d];
        w *= nrm;
        __nv_bfloat16 hi = __float2bfloat16_rn(w);
        __nv_bfloat16 lo = __float2bfloat16_rn(w - __bfloat162float(hi));
        g_Whi[(h * 4 + N) * 256 + d] = hi;
        g_Wlo[(h * 4 + N) * 256 + d] = lo;
    }
    for (int o = tid; o < 1024; o += 256) {
        int N = o >> 8, Do = o & 255;
        float c = 0.f;
#pragma unroll
        for (int n = 0; n < 4; n++) c += C[Do * 256 + h * 4 + n] * sEf[N * 4 + n];
        __nv_bfloat16 hi = __float2bfloat16_rn(c);
        __nv_bfloat16 lo = __float2bfloat16_rn(c - __bfloat162float(hi));
        g_Chi[Do * 256 + h * 4 + N] = hi;
        g_Clo[Do * 256 + h * 4 + N] = lo;
    }
}

// ============================================================================
// Transpose u [b][d][t] -> u^T hi/lo bf16 [b][t][d]
// ============================================================================
__global__ __launch_bounds__(256) void transp_kernel(const float* __restrict__ U)
{
    __shared__ float s[64][65];
    int b = blockIdx.z, d0 = blockIdx.y * 64, t0 = blockIdx.x * 64;
    const float* Ub = U + ((long)b * DH + d0) * TLEN;
    int tid = threadIdx.x;
#pragma unroll
    for (int i = 0; i < 4; i++) {
        int lin = tid + i * 256;
        int r = lin >> 4, c4 = (lin & 15) << 2;
        float4 v = *(const float4*)&Ub[(long)r * TLEN + t0 + c4];
        s[r][c4] = v.x; s[r][c4 + 1] = v.y; s[r][c4 + 2] = v.z; s[r][c4 + 3] = v.w;
    }
    __syncthreads();
#pragma unroll
    for (int i = 0; i < 4; i++) {
        int lin = tid + i * 256;
        int tr = lin >> 4, dc = (lin & 15) << 2;
        long oidx = ((long)b * TLEN + t0 + tr) * 256 + d0 + dc;
        __nv_bfloat162 h2a, h2b, l2a, l2b;
        float v0 = s[dc + 0][tr], v1 = s[dc + 1][tr], v2 = s[dc + 2][tr], v3 = s[dc + 3][tr];
        h2a.x = __float2bfloat16_rn(v0); l2a.x = __float2bfloat16_rn(v0 - __bfloat162float(h2a.x));
        h2a.y = __float2bfloat16_rn(v1); l2a.y = __float2bfloat16_rn(v1 - __bfloat162float(h2a.y));
        h2b.x = __float2bfloat16_rn(v2); l2b.x = __float2bfloat16_rn(v2 - __bfloat162float(h2b.x));
        h2b.y = __float2bfloat16_rn(v3); l2b.y = __float2bfloat16_rn(v3 - __bfloat162float(h2b.y));
        *(__nv_bfloat162*)&g_UThi[oidx]     = h2a;
        *(__nv_bfloat162*)&g_UThi[oidx + 2] = h2b;
        *(__nv_bfloat162*)&g_UTlo[oidx]     = l2a;
        *(__nv_bfloat162*)&g_UTlo[oidx + 2] = l2b;
    }
}

// ============================================================================
// mma.sync GEMM. MODE 0: V[b][n][t] = W @ uT^T.  MODE 1: Y = C_eff @ S^T + D*u.
// C[m][t] = sum_k A[m][k] * B[t][k]; block 128x128, 8 warps of 64x32.
// K streamed as 3 passes (hi*hi, hi*lo, lo*hi) x 8 chunks of 32.
// ============================================================================
template <int MODE>
__global__ __launch_bounds__(256, 2) void mma_gemm_kernel(const float* __restrict__ U,
                                                          const float* __restrict__ Dvec,
                                                          float* __restrict__ Yout)
{
    __shared__ __align__(128) __nv_bfloat16 sA[2][128 * 32];
    __shared__ __align__(128) __nv_bfloat16 sB[2][128 * 32];

    int tid = threadIdx.x, lid = tid & 31, wid = tid >> 5;
    int warp_m = wid & 1, warp_t = wid >> 1;
    int b = blockIdx.z, t0 = blockIdx.x * 128, m0 = blockIdx.y * 128;

    const __nv_bfloat16* Ahi = (MODE == 0) ? g_Whi  : g_Chi;
    const __nv_bfloat16* Alo = (MODE == 0) ? g_Wlo  : g_Clo;
    const __nv_bfloat16* Bhi = (MODE == 0) ? g_UThi : g_Shi;
    const __nv_bfloat16* Blo = (MODE == 0) ? g_UTlo : g_Slo;
    long brow0 = (long)b * TLEN + t0;

    uint32_t aB[2] = { smem_u32(sA[0]), smem_u32(sA[1]) };
    uint32_t bB[2] = { smem_u32(sB[0]), smem_u32(sB[1]) };

    float acc[4][4][4];
#pragma unroll
    for (int mi = 0; mi < 4; mi++)
#pragma unroll
        for (int j = 0; j < 4; j++)
#pragma unroll
            for (int q = 0; q < 4; q++) acc[mi][j][q] = 0.f;

    // per-thread load slots: 4 x 16B (2 for A, 2 for B)
    int qa = tid;                       // A: q in [0,512): r=q>>2, ch=q&3
    // chunk loader
    auto load_chunk = [&](int cs, int buf) {
        int pass = cs >> 3, k0 = (cs & 7) * 32;
        const __nv_bfloat16* As = (pass == 2) ? Alo : Ahi;
        const __nv_bfloat16* Bs = (pass == 1) ? Blo : Bhi;
#pragma unroll
        for (int i = 0; i < 2; i++) {
            int q = qa + i * 256;
            int r = q >> 2, ch = q & 3;
            cpa16(aB[buf] + swz64(r, ch), As + (long)(m0 + r) * 256 + k0 + ch * 8);
        }
#pragma unroll
        for (int i = 0; i < 2; i++) {
            int q = qa + i * 256;
            int r = q >> 2, ch = q & 3;
            cpa16(bB[buf] + swz64(r, ch), Bs + (brow0 + r) * 256 + k0 + ch * 8);
        }
        cpa_commit();
    };

    load_chunk(0, 0);
    for (int cs = 0; cs < 24; cs++) {
        int buf = cs & 1;
        if (cs + 1 < 24) {
            load_chunk(cs + 1, buf ^ 1);
            asm volatile("cp.async.wait_group 1;" ::: "memory");
        } else {
            asm volatile("cp.async.wait_group 0;" ::: "memory");
        }
        __syncthreads();

#pragma unroll
        for (int kk = 0; kk < 2; kk++) {
            int chb = kk * 2 + (lid >> 4);
            uint32_t bf[2][4];
#pragma unroll
            for (int nb = 0; nb < 2; nb++) {
                int tr = warp_t * 32 + nb * 16 + (lid & 15);
                ldmx4(bf[nb], bB[buf] + swz64(tr, chb));
            }
            uint32_t af[4][4];
#pragma unroll
            for (int mi = 0; mi < 4; mi++) {
                int r = warp_m * 64 + mi * 16 + (lid & 15);
                ldmx4(af[mi], aB[buf] + swz64(r, chb));
            }
#pragma unroll
            for (int mi = 0; mi < 4; mi++)
#pragma unroll
                for (int j = 0; j < 4; j++)
                    mma_bf16(acc[mi][j], af[mi], bf[j >> 1][j & 1], bf[j >> 1][2 + (j & 1)]);
        }
        __syncthreads();
    }

    // epilogue
    int cbase = t0 + warp_t * 32 + 2 * (lid & 3);
#pragma unroll
    for (int mi = 0; mi < 4; mi++) {
#pragma unroll
        for (int h = 0; h < 2; h++) {
            int row = m0 + warp_m * 64 + mi * 16 + (lid >> 2) + h * 8;
            if (MODE == 0) {
                float* vrow = g_V + ((long)b * DH + row) * TLEN;
#pragma unroll
                for (int j = 0; j < 4; j++)
                    *(float2*)&vrow[cbase + j * 8] =
                        make_float2(acc[mi][j][2 * h], acc[mi][j][2 * h + 1]);
            } else {
                float dv = Dvec[row];
                const float* urow = U    + ((long)b * DH + row) * TLEN;
                float*       yrow = Yout + ((long)b * DH + row) * TLEN;
#pragma unroll
                for (int j = 0; j < 4; j++) {
                    float2 u2 = *(const float2*)&urow[cbase + j * 8];
                    *(float2*)&yrow[cbase + j * 8] =
                        make_float2(acc[mi][j][2 * h]     + dv * u2.x,
                                    acc[mi][j][2 * h + 1] + dv * u2.y);
                }
            }
        }
    }
}

// ============================================================================
// Scan over t: reads V [b][n][t] fp32, writes S hi/lo bf16 [b][t][n].
// ============================================================================
__global__ __launch_bounds__(NPAIR) void scan_kernel()
{
    int b = blockIdx.x & 7, chunk = blockIdx.x >> 3, p = threadIdx.x;
    float2 lam = g_lam[p];
    float lc = lam.x, ls = lam.y;
    long r0 = ((long)b * DH + 2 * p) * TLEN + chunk * LCHUNK;
    long r1 = r0 + TLEN;

    float s0 = 0.f, s1 = 0.f;
    for (int t = 0; t < LCHUNK; t += 4) {
        float4 vx = *(const float4*)&g_V[r0 + t];
        float4 vy = *(const float4*)&g_V[r1 + t];
        float n0, n1;
        n0 = fmaf(lc, s0, fmaf(-ls, s1, vx.x)); n1 = fmaf(ls, s0, fmaf(lc, s1, vy.x)); s0 = n0; s1 = n1;
        n0 = fmaf(lc, s0, fmaf(-ls, s1, vx.y)); n1 = fmaf(ls, s0, fmaf(lc, s1, vy.y)); s0 = n0; s1 = n1;
        n0 = fmaf(lc, s0, fmaf(-ls, s1, vx.z)); n1 = fmaf(ls, s0, fmaf(lc, s1, vy.z)); s0 = n0; s1 = n1;
        n0 = fmaf(lc, s0, fmaf(-ls, s1, vx.w)); n1 = fmaf(ls, s0, fmaf(lc, s1, vy.w)); s0 = n0; s1 = n1;
    }

    float e0 = 0.f, e1 = 0.f;
    int idx = b * NCHUNK + chunk;
    if (chunk > 0) {
        int prev = idx - 1;
        if (p == 0) {
            while (atomicAdd(&g_flag[prev], 0) == 0) __nanosleep(40);
        }
        __syncthreads();
        float2 e = __ldcg(&g_carry[prev * NPAIR + p]);
        e0 = e.x; e1 = e.y;
    }
    float2 mL = g_lamL[p];
    float i0 = fmaf(mL.x, e0, fmaf(-mL.y, e1, s0));
    float i1 = fmaf(mL.y, e0, fmaf( mL.x, e1, s1));
    __stcg(&g_carry[idx * NPAIR + p], make_float2(i0, i1));
    __threadfence();
    __syncthreads();
    if (p == 0) atomicExch(&g_flag[idx], 1);

    s0 = e0; s1 = e1;
    long obase = ((long)b * TLEN + chunk * LCHUNK) * 256 + 2 * p;
    for (int t = 0; t < LCHUNK; t += 4) {
        float4 vx = *(const float4*)&g_V[r0 + t];
        float4 vy = *(const float4*)&g_V[r1 + t];
#pragma unroll
        for (int q = 0; q < 4; q++) {
            float ux = (q == 0) ? vx.x : (q == 1) ? vx.y : (q == 2) ? vx.z : vx.w;
            float uy = (q == 0) ? vy.x : (q == 1) ? vy.y : (q == 2) ? vy.z : vy.w;
            float n0 = fmaf(lc, s0, fmaf(-ls, s1, ux));
            float n1 = fmaf(ls, s0, fmaf( lc, s1, uy));
            s0 = n0; s1 = n1;
            __nv_bfloat162 h2, l2;
            h2.x = __float2bfloat16_rn(s0); l2.x = __float2bfloat16_rn(s0 - __bfloat162float(h2.x));
            h2.y = __float2bfloat16_rn(s1); l2.y = __float2bfloat16_rn(s1 - __bfloat162float(h2.y));
            long oi = obase + (long)(t + q) * 256;
            *(__nv_bfloat162*)&g_Shi[oi] = h2;
            *(__nv_bfloat162*)&g_Slo[oi] = l2;
        }
    }
}

// ============================================================================
extern "C" void kernel_launch(void* const* d_in, const int* in_sizes, int n_in,
                              void* d_out, int out_size)
{
    const float* u          = (const float*)d_in[0];
    const float* thetas_log = (const float*)d_in[1];
    const float* P_param    = (const float*)d_in[2];
    const float* B_param    = (const float*)d_in[3];
    const float* C          = (const float*)d_in[4];
    const float* Dv         = (const float*)d_in[5];
    const float* gamma_log  = (const float*)d_in[6];
    float* Y = (float*)d_out;

    setup_kernel<<<64, 256>>>(thetas_log, P_param, B_param, C, gamma_log);
    transp_kernel<<<dim3(TLEN / 64, DH / 64, BSZ), 256>>>(u);
    mma_gemm_kernel<0><<<dim3(TLEN / 128, 2, BSZ), 256>>>(nullptr, nullptr, nullptr);
    scan_kernel<<<BSZ * NCHUNK, NPAIR>>>();
    mma_gemm_kernel<1><<<dim3(TLEN / 128, 2, BSZ), 256>>>(u, Dv, Y);
}

// round 5
// speedup vs baseline: 2.1692x; 1.0380x over previous
#include <cuda_runtime.h>
#include <cuda_bf16.h>
#include <cstdint>

#define BSZ    8
#define TLEN   4096
#define DH     256
#define NPAIR  128
#define LCHUNK 256
#define NCHUNK (TLEN / LCHUNK)   // 16

// ---------------- device scratch (static; no allocations) ----------------
__device__ __align__(16) __nv_bfloat16 g_Whi[DH * DH];   // W [n][d]
__device__ __align__(16) __nv_bfloat16 g_Wlo[DH * DH];
__device__ __align__(16) __nv_bfloat16 g_Chi[DH * DH];   // C_eff [dout][n]
__device__ __align__(16) __nv_bfloat16 g_Clo[DH * DH];
__device__ __align__(16) __nv_bfloat16 g_UThi[BSZ * TLEN * DH];  // u^T [b][t][d]
__device__ __align__(16) __nv_bfloat16 g_UTlo[BSZ * TLEN * DH];
__device__ __align__(16) float         g_V   [BSZ * TLEN * DH];  // [b][t][n]
__device__ __align__(16) __nv_bfloat16 g_Shi[BSZ * TLEN * DH];   // [b][t][n]
__device__ __align__(16) __nv_bfloat16 g_Slo[BSZ * TLEN * DH];
__device__ float2 g_lam  [NPAIR];   // lambda
__device__ float2 g_lam32[NPAIR];   // lambda^32
__device__ float2 g_lamL [NPAIR];   // lambda^LCHUNK
__device__ float2 g_carry[BSZ * NCHUNK * NPAIR];
__device__ int    g_flag [BSZ * NCHUNK];

// ---------------- PTX helpers (all sm_80+ portable) ----------------
__device__ __forceinline__ uint32_t smem_u32(const void* p) {
    uint32_t a;
    asm("{ .reg .u64 t; cvta.to.shared.u64 t, %1; cvt.u32.u64 %0, t; }" : "=r"(a) : "l"(p));
    return a;
}
__device__ __forceinline__ void cpa16(uint32_t dst, const void* src) {
    asm volatile("cp.async.cg.shared.global [%0], [%1], 16;" :: "r"(dst), "l"(src));
}
__device__ __forceinline__ void cpa_commit() { asm volatile("cp.async.commit_group;"); }

__device__ __forceinline__ void ldmx4(uint32_t* r, uint32_t addr) {
    asm volatile("ldmatrix.sync.aligned.m8n8.x4.shared.b16 {%0,%1,%2,%3}, [%4];"
                 : "=r"(r[0]), "=r"(r[1]), "=r"(r[2]), "=r"(r[3]) : "r"(addr));
}
__device__ __forceinline__ void mma_bf16(float* c, const uint32_t* a, uint32_t b0, uint32_t b1) {
    asm volatile("mma.sync.aligned.m16n8k16.row.col.f32.bf16.bf16.f32 "
                 "{%0,%1,%2,%3}, {%4,%5,%6,%7}, {%8,%9}, {%0,%1,%2,%3};"
                 : "+f"(c[0]), "+f"(c[1]), "+f"(c[2]), "+f"(c[3])
                 : "r"(a[0]), "r"(a[1]), "r"(a[2]), "r"(a[3]), "r"(b0), "r"(b1));
}
// xor swizzle for 64B rows (4 x 16B chunks): conflict-free ldmatrix + cp.async
__device__ __forceinline__ uint32_t swz64(int r, int ch) {
    return (uint32_t)(r * 64 + ((ch ^ ((r >> 1) & 3)) << 4));
}

// ============================================================================
// Setup: expm(skew) per head, fold into W=[n][d] and C_eff=[dout][n] (bf16 hi/lo)
// ============================================================================
__global__ void setup_kernel(const float* __restrict__ thetas_log,
                             const float* __restrict__ P_param,
                             const float* __restrict__ B_param,
                             const float* __restrict__ C,
                             const float* __restrict__ gamma_log)
{
    int h = blockIdx.x, tid = threadIdx.x;
    __shared__ double sA[16], sEd[16], sTm[16], sTmp[16];
    __shared__ float  sRed[256], sEf[16], sNrm;

    if (h == 0 && tid < BSZ * NCHUNK) g_flag[tid] = 0;

    float part = 0.f;
    for (int i = tid; i < 1024; i += 256) {
        float v = B_param[h * 1024 + i];
        part += v * v;
    }
    sRed[tid] = part;
    __syncthreads();
    for (int s = 128; s > 0; s >>= 1) {
        if (tid < s) sRed[tid] += sRed[tid + s];
        __syncthreads();
    }
    if (tid < 16) {
        int i = tid >> 2, j = tid & 3;
        sA[tid]  = (double)P_param[h * 16 + tid] - (double)P_param[h * 16 + j * 4 + i];
        sEd[tid] = (i == j) ? 1.0 : 0.0;
        sTm[tid] = sEd[tid];
    }
    __syncthreads();
    for (int k = 1; k <= 24; ++k) {
        if (tid < 16) {
            int i = tid >> 2, j = tid & 3;
            double acc = 0.0;
#pragma unroll
            for (int m = 0; m < 4; m++) acc += sTm[i * 4 + m] * sA[m * 4 + j];
            sTmp[tid] = acc / (double)k;
        }
        __syncthreads();
        if (tid < 16) { sTm[tid] = sTmp[tid]; sEd[tid] += sTmp[tid]; }
        __syncthreads();
    }
    if (tid == 0) {
        double gl = (double)gamma_log[h], eg = exp(gl), gamma = exp(-eg);
        sNrm = (float)sqrt((1.0 - gamma * gamma) / (double)sRed[0]);
        double g32 = exp(-32.0 * eg);
        double gL  = exp(-(double)LCHUNK * eg);
        const double TWO_PI = 6.283185307179586476925286766559;
        for (int j = 0; j < 2; j++) {
            double th = exp((double)thetas_log[h * 2 + j]);
            g_lam[h * 2 + j] = make_float2((float)(gamma * cos(th)), (float)(gamma * sin(th)));
            double a32 = fmod(32.0 * th, TWO_PI);
            g_lam32[h * 2 + j] = make_float2((float)(g32 * cos(a32)), (float)(g32 * sin(a32)));
            double aL = fmod((double)LCHUNK * th, TWO_PI);
            g_lamL[h * 2 + j] = make_float2((float)(gL * cos(aL)), (float)(gL * sin(aL)));
        }
    }
    if (tid < 16) sEf[tid] = (float)sEd[tid];
    __syncthreads();
    float nrm = sNrm;
    for (int o = tid; o < 1024; o += 256) {
        int N = o >> 8, d = o & 255;
        float w = 0.f;
#pragma unroll
        for (int n = 0; n < 4; n++) w += sEf[N * 4 + n] * B_param[h * 1024 + n * 256 + d];
        w *= nrm;
        __nv_bfloat16 hi = __float2bfloat16_rn(w);
        __nv_bfloat16 lo = __float2bfloat16_rn(w - __bfloat162float(hi));
        g_Whi[(h * 4 + N) * 256 + d] = hi;
        g_Wlo[(h * 4 + N) * 256 + d] = lo;
    }
    for (int o = tid; o < 1024; o += 256) {
        int N = o >> 8, Do = o & 255;
        float c = 0.f;
#pragma unroll
        for (int n = 0; n < 4; n++) c += C[Do * 256 + h * 4 + n] * sEf[N * 4 + n];
        __nv_bfloat16 hi = __float2bfloat16_rn(c);
        __nv_bfloat16 lo = __float2bfloat16_rn(c - __bfloat162float(hi));
        g_Chi[Do * 256 + h * 4 + N] = hi;
        g_Clo[Do * 256 + h * 4 + N] = lo;
    }
}

// ============================================================================
// Transpose u [b][d][t] -> u^T hi/lo bf16 [b][t][d]
// ============================================================================
__global__ __launch_bounds__(256) void transp_kernel(const float* __restrict__ U)
{
    __shared__ float s[64][65];
    int b = blockIdx.z, d0 = blockIdx.y * 64, t0 = blockIdx.x * 64;
    const float* Ub = U + ((long)b * DH + d0) * TLEN;
    int tid = threadIdx.x;
#pragma unroll
    for (int i = 0; i < 4; i++) {
        int lin = tid + i * 256;
        int r = lin >> 4, c4 = (lin & 15) << 2;
        float4 v = *(const float4*)&Ub[(long)r * TLEN + t0 + c4];
        s[r][c4] = v.x; s[r][c4 + 1] = v.y; s[r][c4 + 2] = v.z; s[r][c4 + 3] = v.w;
    }
    __syncthreads();
#pragma unroll
    for (int i = 0; i < 4; i++) {
        int lin = tid + i * 256;
        int tr = lin >> 4, dc = (lin & 15) << 2;
        long oidx = ((long)b * TLEN + t0 + tr) * 256 + d0 + dc;
        __nv_bfloat162 h2a, h2b, l2a, l2b;
        float v0 = s[dc + 0][tr], v1 = s[dc + 1][tr], v2 = s[dc + 2][tr], v3 = s[dc + 3][tr];
        h2a.x = __float2bfloat16_rn(v0); l2a.x = __float2bfloat16_rn(v0 - __bfloat162float(h2a.x));
        h2a.y = __float2bfloat16_rn(v1); l2a.y = __float2bfloat16_rn(v1 - __bfloat162float(h2a.y));
        h2b.x = __float2bfloat16_rn(v2); l2b.x = __float2bfloat16_rn(v2 - __bfloat162float(h2b.x));
        h2b.y = __float2bfloat16_rn(v3); l2b.y = __float2bfloat16_rn(v3 - __bfloat162float(h2b.y));
        *(__nv_bfloat162*)&g_UThi[oidx]     = h2a;
        *(__nv_bfloat162*)&g_UThi[oidx + 2] = h2b;
        *(__nv_bfloat162*)&g_UTlo[oidx]     = l2a;
        *(__nv_bfloat162*)&g_UTlo[oidx + 2] = l2b;
    }
}

// ============================================================================
// mma.sync GEMM. MODE 0: V[b][t][n] = (W @ uT^T)^T.  MODE 1: Y = C_eff @ S^T + D*u.
// C[m][t] = sum_k A[m][k] * B[t][k]; block 128x128, 8 warps of 64x32.
// K streamed as 3 passes (hi*hi, hi*lo, lo*hi) x 8 chunks of 32.
// ============================================================================
template <int MODE>
__global__ __launch_bounds__(256, 2) void mma_gemm_kernel(const float* __restrict__ U,
                                                          const float* __restrict__ Dvec,
                                                          float* __restrict__ Yout)
{
    __shared__ __align__(128) __nv_bfloat16 sA[2][128 * 32];
    __shared__ __align__(128) __nv_bfloat16 sB[2][128 * 32];

    int tid = threadIdx.x, lid = tid & 31, wid = tid >> 5;
    int warp_m = wid & 1, warp_t = wid >> 1;
    int b = blockIdx.z, t0 = blockIdx.x * 128, m0 = blockIdx.y * 128;

    const __nv_bfloat16* Ahi = (MODE == 0) ? g_Whi  : g_Chi;
    const __nv_bfloat16* Alo = (MODE == 0) ? g_Wlo  : g_Clo;
    const __nv_bfloat16* Bhi = (MODE == 0) ? g_UThi : g_Shi;
    const __nv_bfloat16* Blo = (MODE == 0) ? g_UTlo : g_Slo;
    long brow0 = (long)b * TLEN + t0;

    uint32_t aB[2] = { smem_u32(sA[0]), smem_u32(sA[1]) };
    uint32_t bB[2] = { smem_u32(sB[0]), smem_u32(sB[1]) };

    float acc[4][4][4];
#pragma unroll
    for (int mi = 0; mi < 4; mi++)
#pragma unroll
        for (int j = 0; j < 4; j++)
#pragma unroll
            for (int q = 0; q < 4; q++) acc[mi][j][q] = 0.f;

    int qa = tid;
    auto load_chunk = [&](int cs, int buf) {
        int pass = cs >> 3, k0 = (cs & 7) * 32;
        const __nv_bfloat16* As = (pass == 2) ? Alo : Ahi;
        const __nv_bfloat16* Bs = (pass == 1) ? Blo : Bhi;
#pragma unroll
        for (int i = 0; i < 2; i++) {
            int q = qa + i * 256;
            int r = q >> 2, ch = q & 3;
            cpa16(aB[buf] + swz64(r, ch), As + (long)(m0 + r) * 256 + k0 + ch * 8);
        }
#pragma unroll
        for (int i = 0; i < 2; i++) {
            int q = qa + i * 256;
            int r = q >> 2, ch = q & 3;
            cpa16(bB[buf] + swz64(r, ch), Bs + (brow0 + r) * 256 + k0 + ch * 8);
        }
        cpa_commit();
    };

    load_chunk(0, 0);
    for (int cs = 0; cs < 24; cs++) {
        int buf = cs & 1;
        if (cs + 1 < 24) {
            load_chunk(cs + 1, buf ^ 1);
            asm volatile("cp.async.wait_group 1;" ::: "memory");
        } else {
            asm volatile("cp.async.wait_group 0;" ::: "memory");
        }
        __syncthreads();

#pragma unroll
        for (int kk = 0; kk < 2; kk++) {
            int chb = kk * 2 + (lid >> 4);
            uint32_t bf[2][4];
#pragma unroll
            for (int nb = 0; nb < 2; nb++) {
                int tr = warp_t * 32 + nb * 16 + (lid & 15);
                ldmx4(bf[nb], bB[buf] + swz64(tr, chb));
            }
            uint32_t af[4][4];
#pragma unroll
            for (int mi = 0; mi < 4; mi++) {
                int r = warp_m * 64 + mi * 16 + (lid & 15);
                ldmx4(af[mi], aB[buf] + swz64(r, chb));
            }
#pragma unroll
            for (int mi = 0; mi < 4; mi++)
#pragma unroll
                for (int j = 0; j < 4; j++)
                    mma_bf16(acc[mi][j], af[mi], bf[j >> 1][j & 1], bf[j >> 1][2 + (j & 1)]);
        }
        __syncthreads();
    }

    // epilogue
    int cbase = t0 + warp_t * 32 + 2 * (lid & 3);
#pragma unroll
    for (int mi = 0; mi < 4; mi++) {
#pragma unroll
        for (int h = 0; h < 2; h++) {
            int row = m0 + warp_m * 64 + mi * 16 + (lid >> 2) + h * 8;
            if (MODE == 0) {
                // write V in [b][t][n]: n = row (contiguous), t = column
#pragma unroll
                for (int j = 0; j < 4; j++) {
                    long basev = ((long)b * TLEN + cbase + j * 8) * 256 + row;
                    g_V[basev]       = acc[mi][j][2 * h];
                    g_V[basev + 256] = acc[mi][j][2 * h + 1];
                }
            } else {
                float dv = Dvec[row];
                const float* urow = U    + ((long)b * DH + row) * TLEN;
                float*       yrow = Yout + ((long)b * DH + row) * TLEN;
#pragma unroll
                for (int j = 0; j < 4; j++) {
                    float2 u2 = *(const float2*)&urow[cbase + j * 8];
                    *(float2*)&yrow[cbase + j * 8] =
                        make_float2(acc[mi][j][2 * h]     + dv * u2.x,
                                    acc[mi][j][2 * h + 1] + dv * u2.y);
                }
            }
        }
    }
}

// ============================================================================
// Scan over t on V [b][t][n]. Block = 1024 threads = 128 pairs x 8 sub-chunks
// of 32 steps (LCHUNK=256). Coalesced loads; decoupled chunk lookback.
// Writes S hi/lo bf16 [b][t][n].
// ============================================================================
__global__ __launch_bounds__(1024, 1) void scan_kernel()
{
    __shared__ float2 sLoc[8][NPAIR];
    __shared__ float2 sExc[8][NPAIR];
    __shared__ float2 sAgg[NPAIR];
    __shared__ float2 sE[NPAIR];

    int b = blockIdx.x & 7, chunk = blockIdx.x >> 3;
    int tid = threadIdx.x, p = tid & 127, sc = tid >> 7;
    float2 lam = g_lam[p];
    float lc = lam.x, ls = lam.y;
    float2 l32 = g_lam32[p];
    long vbase = ((long)b * TLEN + chunk * LCHUNK + sc * 32) * 256 + 2 * p;

    // phase 1: local sub-chunk scan from zero
    float s0 = 0.f, s1 = 0.f;
#pragma unroll 4
    for (int t = 0; t < 32; t++) {
        float2 v = *(const float2*)&g_V[vbase + (long)t * 256];
        float n0 = fmaf(lc, s0, fmaf(-ls, s1, v.x));
        float n1 = fmaf(ls, s0, fmaf( lc, s1, v.y));
        s0 = n0; s1 = n1;
    }
    sLoc[sc][p] = make_float2(s0, s1);
    __syncthreads();

    // combine sub-chunk carries (serial over 8, one thread per pair)
    if (tid < NPAIR) {
        float i0 = 0.f, i1 = 0.f;
#pragma unroll
        for (int k = 0; k < 8; k++) {
            sExc[k][p] = make_float2(i0, i1);
            float2 lo = sLoc[k][p];
            float a0 = fmaf(l32.x, i0, fmaf(-l32.y, i1, lo.x));
            float a1 = fmaf(l32.y, i0, fmaf( l32.x, i1, lo.y));
            i0 = a0; i1 = a1;
        }
        sAgg[p] = make_float2(i0, i1);
    }
    __syncthreads();

    // chunk-level decoupled lookback
    int idx = b * NCHUNK + chunk;
    if (chunk > 0 && tid == 0) {
        while (atomicAdd(&g_flag[idx - 1], 0) == 0) __nanosleep(40);
    }
    __syncthreads();
    if (tid < NPAIR) {
        float e0 = 0.f, e1 = 0.f;
        if (chunk > 0) {
            float2 e = __ldcg(&g_carry[(idx - 1) * NPAIR + p]);
            e0 = e.x; e1 = e.y;
        }
        float2 agg = sAgg[p];
        float2 mL = g_lamL[p];
        float i0 = fmaf(mL.x, e0, fmaf(-mL.y, e1, agg.x));
        float i1 = fmaf(mL.y, e0, fmaf( mL.x, e1, agg.y));
        __stcg(&g_carry[idx * NPAIR + p], make_float2(i0, i1));
        __threadfence();
        sE[p] = make_float2(e0, e1);
    }
    __syncthreads();
    if (tid == 0) {
        __threadfence();
        atomicExch(&g_flag[idx], 1);
    }

    // start state = lambda^(32*sc) * E + exclusive_within(sc)
    float2 E = sE[p];
    float m0 = 1.f, m1 = 0.f;
    for (int i = 0; i < sc; i++) {
        float a0 = m0 * l32.x - m1 * l32.y;
        float a1 = m0 * l32.y + m1 * l32.x;
        m0 = a0; m1 = a1;
    }
    float2 ex = sExc[sc][p];
    s0 = fmaf(m0, E.x, fmaf(-m1, E.y, ex.x));
    s1 = fmaf(m1, E.x, fmaf( m0, E.y, ex.y));

    // phase 2: rescan + emit bf16 hi/lo
#pragma unroll 4
    for (int t = 0; t < 32; t++) {
        float2 v = *(const float2*)&g_V[vbase + (long)t * 256];
        float n0 = fmaf(lc, s0, fmaf(-ls, s1, v.x));
        float n1 = fmaf(ls, s0, fmaf( lc, s1, v.y));
        s0 = n0; s1 = n1;
        __nv_bfloat162 h2, l2;
        h2.x = __float2bfloat16_rn(s0); l2.x = __float2bfloat16_rn(s0 - __bfloat162float(h2.x));
        h2.y = __float2bfloat16_rn(s1); l2.y = __float2bfloat16_rn(s1 - __bfloat162float(h2.y));
        *(__nv_bfloat162*)&g_Shi[vbase + (long)t * 256] = h2;
        *(__nv_bfloat162*)&g_Slo[vbase + (long)t * 256] = l2;
    }
}

// ============================================================================
extern "C" void kernel_launch(void* const* d_in, const int* in_sizes, int n_in,
                              void* d_out, int out_size)
{
    const float* u          = (const float*)d_in[0];
    const float* thetas_log = (const float*)d_in[1];
    const float* P_param    = (const float*)d_in[2];
    const float* B_param    = (const float*)d_in[3];
    const float* C          = (const float*)d_in[4];
    const float* Dv         = (const float*)d_in[5];
    const float* gamma_log  = (const float*)d_in[6];
    float* Y = (float*)d_out;

    setup_kernel<<<64, 256>>>(thetas_log, P_param, B_param, C, gamma_log);
    transp_kernel<<<dim3(TLEN / 64, DH / 64, BSZ), 256>>>(u);
    mma_gemm_kernel<0><<<dim3(TLEN / 128, 2, BSZ), 256>>>(nullptr, nullptr, nullptr);
    scan_kernel<<<BSZ * NCHUNK, 1024>>>();
    mma_gemm_kernel<1><<<dim3(TLEN / 128, 2, BSZ), 256>>>(u, Dv, Y);
}